// round 1
// baseline (speedup 1.0000x reference)
#include <cuda_runtime.h>
#include <math.h>

#define BB 2
#define SS 2048
#define DD 1024
#define HH 16
#define HDIM 64
#define NR (BB*SS)            // 4096 rows
#define ATT_SCALE 0.125f      // 1/sqrt(64)

// ---------------- device scratch (no cudaMalloc allowed) ----------------
static __device__ float g_W3[3 * DD * DD];          // concat(Wq,Wk,Wv) rows
static __device__ float g_b3[3 * DD];
static __device__ float g_QKV[(size_t)NR * 3 * DD]; // (4096, 3072): Q|K|V
static __device__ float g_C[(size_t)NR * DD];       // ctx (B,S,D)

// ---------------- weight concat ----------------
__global__ void concat_kernel(const float* __restrict__ Wq, const float* __restrict__ Wk,
                              const float* __restrict__ Wv, const float* __restrict__ bq,
                              const float* __restrict__ bk, const float* __restrict__ bv) {
    int i = blockIdx.x * 256 + threadIdx.x;
    if (i < DD * DD) {
        g_W3[i]             = Wq[i];
        g_W3[DD * DD + i]   = Wk[i];
        g_W3[2 * DD * DD + i] = Wv[i];
    }
    if (i < DD) {
        g_b3[i]        = bq[i];
        g_b3[DD + i]   = bk[i];
        g_b3[2*DD + i] = bv[i];
    }
}

// ---------------- NT SGEMM: C[M,N] = A[M,K] @ B[N,K]^T + bias ----------------
// 128x128 tile, BK=16, 8x8 per thread, swizzled K-major smem.
__global__ __launch_bounds__(256) void gemm_nt_bias(
    const float* __restrict__ A, const float* __restrict__ Bw,
    const float* __restrict__ bias, float* __restrict__ C,
    int M, int N, int K)
{
    __shared__ float As[16][128];
    __shared__ float Bs[16][128];
    const int t  = threadIdx.x;
    const int tx = t & 15, ty = t >> 4;
    const int row0 = blockIdx.y * 128;
    const int col0 = blockIdx.x * 128;
    const int lkv  = t & 3;       // which float4 of the 16-wide k slab

    float acc[8][8];
#pragma unroll
    for (int i = 0; i < 8; i++)
#pragma unroll
        for (int j = 0; j < 8; j++) acc[i][j] = 0.f;

    for (int k0 = 0; k0 < K; k0 += 16) {
#pragma unroll
        for (int half = 0; half < 2; half++) {
            const int r  = (t >> 2) + half * 64;          // 0..127
            const int pc = (((r >> 3) ^ lkv) << 3) | (r & 7);  // swizzled column
            float4 va = *(const float4*)(&A [(size_t)(row0 + r) * K + k0 + lkv * 4]);
            As[lkv*4+0][pc] = va.x; As[lkv*4+1][pc] = va.y;
            As[lkv*4+2][pc] = va.z; As[lkv*4+3][pc] = va.w;
            float4 vb = *(const float4*)(&Bw[(size_t)(col0 + r) * K + k0 + lkv * 4]);
            Bs[lkv*4+0][pc] = vb.x; Bs[lkv*4+1][pc] = vb.y;
            Bs[lkv*4+2][pc] = vb.z; Bs[lkv*4+3][pc] = vb.w;
        }
        __syncthreads();
#pragma unroll
        for (int kk = 0; kk < 16; kk++) {
            const int s = kk >> 2;
            float a[8], b[8];
            *(float4*)&a[0] = *(const float4*)&As[kk][((ty ^ s) << 3)];
            *(float4*)&a[4] = *(const float4*)&As[kk][((ty ^ s) << 3) + 4];
            *(float4*)&b[0] = *(const float4*)&Bs[kk][((tx ^ s) << 3)];
            *(float4*)&b[4] = *(const float4*)&Bs[kk][((tx ^ s) << 3) + 4];
#pragma unroll
            for (int i = 0; i < 8; i++)
#pragma unroll
                for (int j = 0; j < 8; j++)
                    acc[i][j] = fmaf(a[i], b[j], acc[i][j]);
        }
        __syncthreads();
    }

#pragma unroll
    for (int i = 0; i < 8; i++) {
        const size_t r = (size_t)(row0 + ty * 8 + i);
        float* crow = C + r * N + col0 + tx * 8;
#pragma unroll
        for (int j = 0; j < 8; j += 4) {
            float4 v;
            v.x = acc[i][j+0] + bias[col0 + tx*8 + j+0];
            v.y = acc[i][j+1] + bias[col0 + tx*8 + j+1];
            v.z = acc[i][j+2] + bias[col0 + tx*8 + j+2];
            v.w = acc[i][j+3] + bias[col0 + tx*8 + j+3];
            *(float4*)(crow + j) = v;
        }
    }
}

// ---------------- scores: attn_raw[b,h,q,k] = SCALE * Q.K  (lower-tri tiles only) ----
__global__ __launch_bounds__(256) void scores_kernel(
    const float* __restrict__ QKV, float* __restrict__ attn)
{
    const int kt = blockIdx.x, qt = blockIdx.y, z = blockIdx.z;
    if (kt > qt) return;
    const int b = z >> 4, h = z & 15;
    __shared__ float Qs[64][65];
    __shared__ float Kt[64][64];
    const int t = threadIdx.x, tx = t & 15, ty = t >> 4;

    const float* Qb = QKV + ((size_t)(b * SS) + qt * 64) * 3072 + h * 64;
    const float* Kb = QKV + ((size_t)(b * SS) + kt * 64) * 3072 + h * 64 + DD;

    const int lr = t >> 2;
    const int lc = t & 3;
#pragma unroll
    for (int l = 0; l < 4; l++) {
        const int c4 = lc + l * 4;
        float4 vq = *(const float4*)(Qb + (size_t)lr * 3072 + c4 * 4);
        Qs[lr][c4*4+0] = vq.x; Qs[lr][c4*4+1] = vq.y;
        Qs[lr][c4*4+2] = vq.z; Qs[lr][c4*4+3] = vq.w;
        float4 vk = *(const float4*)(Kb + (size_t)lr * 3072 + c4 * 4);
        Kt[c4*4+0][lr] = vk.x; Kt[c4*4+1][lr] = vk.y;
        Kt[c4*4+2][lr] = vk.z; Kt[c4*4+3][lr] = vk.w;
    }
    __syncthreads();

    float acc[4][4];
#pragma unroll
    for (int i = 0; i < 4; i++)
#pragma unroll
        for (int j = 0; j < 4; j++) acc[i][j] = 0.f;

#pragma unroll
    for (int kk = 0; kk < 64; kk++) {
        float a0 = Qs[ty*4+0][kk];
        float a1 = Qs[ty*4+1][kk];
        float a2 = Qs[ty*4+2][kk];
        float a3 = Qs[ty*4+3][kk];
        float4 b4 = *(const float4*)&Kt[kk][tx*4];
        acc[0][0]=fmaf(a0,b4.x,acc[0][0]); acc[0][1]=fmaf(a0,b4.y,acc[0][1]);
        acc[0][2]=fmaf(a0,b4.z,acc[0][2]); acc[0][3]=fmaf(a0,b4.w,acc[0][3]);
        acc[1][0]=fmaf(a1,b4.x,acc[1][0]); acc[1][1]=fmaf(a1,b4.y,acc[1][1]);
        acc[1][2]=fmaf(a1,b4.z,acc[1][2]); acc[1][3]=fmaf(a1,b4.w,acc[1][3]);
        acc[2][0]=fmaf(a2,b4.x,acc[2][0]); acc[2][1]=fmaf(a2,b4.y,acc[2][1]);
        acc[2][2]=fmaf(a2,b4.z,acc[2][2]); acc[2][3]=fmaf(a2,b4.w,acc[2][3]);
        acc[3][0]=fmaf(a3,b4.x,acc[3][0]); acc[3][1]=fmaf(a3,b4.y,acc[3][1]);
        acc[3][2]=fmaf(a3,b4.z,acc[3][2]); acc[3][3]=fmaf(a3,b4.w,acc[3][3]);
    }

    const int qrow = qt * 64 + ty * 4;
    const int kcol = kt * 64 + tx * 4;
#pragma unroll
    for (int i = 0; i < 4; i++) {
        float4 v;
        v.x = acc[i][0] * ATT_SCALE;
        v.y = acc[i][1] * ATT_SCALE;
        v.z = acc[i][2] * ATT_SCALE;
        v.w = acc[i][3] * ATT_SCALE;
        *(float4*)(attn + (((size_t)z * SS + qrow + i) * SS + kcol)) = v;
    }
}

// ---------------- row softmax with causal mask (writes zeros above diag) ----------
__global__ __launch_bounds__(256) void softmax_kernel(float* __restrict__ attn)
{
    const size_t row = blockIdx.x;           // row = z*S + q
    const int q = (int)(row & (SS - 1));
    float* p = attn + row * (size_t)SS;
    const int t = threadIdx.x;

    float v[8];
    float m = -1e30f;
#pragma unroll
    for (int l = 0; l < 8; l++) {
        const int i = t + l * 256;
        v[l] = (i <= q) ? p[i] : -1e30f;
        m = fmaxf(m, v[l]);
    }
#pragma unroll
    for (int o = 16; o > 0; o >>= 1) m = fmaxf(m, __shfl_xor_sync(0xffffffffu, m, o));
    __shared__ float redm[8];
    __shared__ float reds[8];
    if ((t & 31) == 0) redm[t >> 5] = m;
    __syncthreads();
    float bm = redm[0];
#pragma unroll
    for (int w = 1; w < 8; w++) bm = fmaxf(bm, redm[w]);

    float s = 0.f;
#pragma unroll
    for (int l = 0; l < 8; l++) {
        const int i = t + l * 256;
        v[l] = (i <= q) ? __expf(v[l] - bm) : 0.f;
        s += v[l];
    }
#pragma unroll
    for (int o = 16; o > 0; o >>= 1) s += __shfl_xor_sync(0xffffffffu, s, o);
    if ((t & 31) == 0) reds[t >> 5] = s;
    __syncthreads();
    float tot = 0.f;
#pragma unroll
    for (int w = 0; w < 8; w++) tot += reds[w];
    const float inv = 1.0f / tot;
#pragma unroll
    for (int l = 0; l < 8; l++) {
        const int i = t + l * 256;
        p[i] = v[l] * inv;
    }
}

// ---------------- ctx = attn @ V (causal k range) -> g_C (B,S,D layout) ----------
__global__ __launch_bounds__(256) void ctx_kernel(
    const float* __restrict__ attn, const float* __restrict__ QKV,
    float* __restrict__ Cout)
{
    const int qt = blockIdx.x, z = blockIdx.y;
    const int b = z >> 4, h = z & 15;
    __shared__ float Ps[64][65];
    __shared__ float Vs[64][68];
    const int t = threadIdx.x, tx = t & 15, ty = t >> 4;

    const float* Pb = attn + ((size_t)z * SS + qt * 64) * SS;
    const float* Vb = QKV + (size_t)(b * SS) * 3072 + 2 * DD + h * 64;
    const int lr = t >> 2;
    const int lc = t & 3;

    float acc[4][4];
#pragma unroll
    for (int i = 0; i < 4; i++)
#pragma unroll
        for (int j = 0; j < 4; j++) acc[i][j] = 0.f;

    for (int kt = 0; kt <= qt; kt++) {
#pragma unroll
        for (int l = 0; l < 4; l++) {
            const int c4 = lc + l * 4;
            float4 vp = *(const float4*)(Pb + (size_t)lr * SS + kt * 64 + c4 * 4);
            Ps[lr][c4*4+0] = vp.x; Ps[lr][c4*4+1] = vp.y;
            Ps[lr][c4*4+2] = vp.z; Ps[lr][c4*4+3] = vp.w;
            float4 vv = *(const float4*)(Vb + (size_t)(kt * 64 + lr) * 3072 + c4 * 4);
            *(float4*)&Vs[lr][c4*4] = vv;
        }
        __syncthreads();
#pragma unroll
        for (int kk = 0; kk < 64; kk++) {
            float a0 = Ps[ty*4+0][kk];
            float a1 = Ps[ty*4+1][kk];
            float a2 = Ps[ty*4+2][kk];
            float a3 = Ps[ty*4+3][kk];
            float4 b4 = *(const float4*)&Vs[kk][tx*4];
            acc[0][0]=fmaf(a0,b4.x,acc[0][0]); acc[0][1]=fmaf(a0,b4.y,acc[0][1]);
            acc[0][2]=fmaf(a0,b4.z,acc[0][2]); acc[0][3]=fmaf(a0,b4.w,acc[0][3]);
            acc[1][0]=fmaf(a1,b4.x,acc[1][0]); acc[1][1]=fmaf(a1,b4.y,acc[1][1]);
            acc[1][2]=fmaf(a1,b4.z,acc[1][2]); acc[1][3]=fmaf(a1,b4.w,acc[1][3]);
            acc[2][0]=fmaf(a2,b4.x,acc[2][0]); acc[2][1]=fmaf(a2,b4.y,acc[2][1]);
            acc[2][2]=fmaf(a2,b4.z,acc[2][2]); acc[2][3]=fmaf(a2,b4.w,acc[2][3]);
            acc[3][0]=fmaf(a3,b4.x,acc[3][0]); acc[3][1]=fmaf(a3,b4.y,acc[3][1]);
            acc[3][2]=fmaf(a3,b4.z,acc[3][2]); acc[3][3]=fmaf(a3,b4.w,acc[3][3]);
        }
        __syncthreads();
    }

    const int q = qt * 64 + ty * 4;
    const int d = h * 64 + tx * 4;
#pragma unroll
    for (int i = 0; i < 4; i++) {
        float4 v;
        v.x = acc[i][0]; v.y = acc[i][1]; v.z = acc[i][2]; v.w = acc[i][3];
        *(float4*)(Cout + ((size_t)(b * SS) + q + i) * DD + d) = v;
    }
}

// ---------------- launch ----------------
extern "C" void kernel_launch(void* const* d_in, const int* in_sizes, int n_in,
                              void* d_out, int out_size)
{
    const float* x  = (const float*)d_in[0];
    const float* Wq = (const float*)d_in[1];
    const float* bq = (const float*)d_in[2];
    const float* Wk = (const float*)d_in[3];
    const float* bk = (const float*)d_in[4];
    const float* Wv = (const float*)d_in[5];
    const float* bv = (const float*)d_in[6];
    const float* Wo = (const float*)d_in[7];
    const float* bo = (const float*)d_in[8];

    float* out  = (float*)d_out;
    float* attn = out + (size_t)NR * DD;   // tuple order: (out, attn)

    float *pW3, *pb3, *pQKV, *pC;
    cudaGetSymbolAddress((void**)&pW3,  g_W3);
    cudaGetSymbolAddress((void**)&pb3,  g_b3);
    cudaGetSymbolAddress((void**)&pQKV, g_QKV);
    cudaGetSymbolAddress((void**)&pC,   g_C);

    // 1) concat weights/biases
    concat_kernel<<<(DD * DD + 255) / 256, 256>>>(Wq, Wk, Wv, bq, bk, bv);

    // 2) fused QKV projection: (4096 x 3072) = x @ W3^T + b3
    gemm_nt_bias<<<dim3(3072 / 128, NR / 128), 256>>>(x, pW3, pb3, pQKV, NR, 3072, DD);

    // 3) raw causal scores into attn region
    scores_kernel<<<dim3(SS / 64, SS / 64, BB * HH), 256>>>(pQKV, attn);

    // 4) softmax per row (also zero-fills masked region)
    softmax_kernel<<<BB * HH * SS, 256>>>(attn);

    // 5) ctx = attn @ V
    ctx_kernel<<<dim3(SS / 64, BB * HH), 256>>>(attn, pQKV, pC);

    // 6) output projection
    gemm_nt_bias<<<dim3(DD / 128, NR / 128), 256>>>(pC, Wo, bo, out, NR, DD, DD);
}

// round 2
// speedup vs baseline: 1.6858x; 1.6858x over previous
#include <cuda_runtime.h>
#include <stdint.h>
#include <math.h>

#define BB 2
#define SS 2048
#define DD 1024
#define HH 16
#define NR (BB*SS)            // 4096 rows
#define ATT_SCALE 0.125f      // 1/sqrt(64)

// ---------------- device scratch (no cudaMalloc allowed) ----------------
static __device__ float g_W3[3 * DD * DD];          // concat(Wq,Wk,Wv) rows
static __device__ float g_b3[3 * DD];
static __device__ float g_QKV[(size_t)NR * 3 * DD]; // (4096, 3072): Q|K|V
static __device__ float g_C[(size_t)NR * DD];       // ctx (B,S,D)

// ---------------- tf32 helpers ----------------
__device__ __forceinline__ uint32_t f2t(float x) {
    uint32_t r;
    asm("cvt.rna.tf32.f32 %0, %1;" : "=r"(r) : "f"(x));
    return r;
}
__device__ __forceinline__ void mma8(float* c, const uint32_t* a, const uint32_t* b) {
    asm volatile(
        "mma.sync.aligned.m16n8k8.row.col.f32.tf32.tf32.f32 "
        "{%0,%1,%2,%3},{%4,%5,%6,%7},{%8,%9},{%0,%1,%2,%3};"
        : "+f"(c[0]), "+f"(c[1]), "+f"(c[2]), "+f"(c[3])
        : "r"(a[0]), "r"(a[1]), "r"(a[2]), "r"(a[3]), "r"(b[0]), "r"(b[1]));
}

// ---------------- weight concat ----------------
__global__ void concat_kernel(const float* __restrict__ Wq, const float* __restrict__ Wk,
                              const float* __restrict__ Wv, const float* __restrict__ bq,
                              const float* __restrict__ bk, const float* __restrict__ bv) {
    int i = blockIdx.x * 256 + threadIdx.x;
    if (i < DD * DD) {
        g_W3[i]               = Wq[i];
        g_W3[DD * DD + i]     = Wk[i];
        g_W3[2 * DD * DD + i] = Wv[i];
    }
    if (i < DD) {
        g_b3[i]          = bq[i];
        g_b3[DD + i]     = bk[i];
        g_b3[2 * DD + i] = bv[i];
    }
}

// ---------------- NT GEMM (tf32 tensor): C[M,N] = A[M,K] @ B[N,K]^T + bias ----
// 128x128 tile, BK=16, 8 warps (4m x 2n), warp tile 32x64, double-buffered smem.
__global__ __launch_bounds__(256) void gemm_nt_tf32(
    const float* __restrict__ A, const float* __restrict__ Bw,
    const float* __restrict__ bias, float* __restrict__ C,
    int M, int N, int K)
{
    __shared__ uint32_t As[2][128][20];
    __shared__ uint32_t Bs[2][128][20];

    const int t    = threadIdx.x;
    const int lane = t & 31, w = t >> 5;
    const int g    = lane >> 2, tg = lane & 3;
    const int wm   = w & 3, wn = w >> 2;
    const int row0 = blockIdx.y * 128;
    const int col0 = blockIdx.x * 128;

    const int srow = t >> 1;            // 0..127
    const int skq  = (t & 1) * 8;       // 0 or 8
    const float* Ap = A  + (size_t)(row0 + srow) * K + skq;
    const float* Bp = Bw + (size_t)(col0 + srow) * K + skq;

    float acc[2][8][4];
#pragma unroll
    for (int i = 0; i < 2; i++)
#pragma unroll
        for (int j = 0; j < 8; j++)
#pragma unroll
            for (int q = 0; q < 4; q++) acc[i][j][q] = 0.f;

    float4 ra0, ra1, rb0, rb1;
    // prologue: stage k=0 into buffer 0
    ra0 = *(const float4*)(Ap);     ra1 = *(const float4*)(Ap + 4);
    rb0 = *(const float4*)(Bp);     rb1 = *(const float4*)(Bp + 4);
    *(uint4*)&As[0][srow][skq]     = make_uint4(f2t(ra0.x), f2t(ra0.y), f2t(ra0.z), f2t(ra0.w));
    *(uint4*)&As[0][srow][skq + 4] = make_uint4(f2t(ra1.x), f2t(ra1.y), f2t(ra1.z), f2t(ra1.w));
    *(uint4*)&Bs[0][srow][skq]     = make_uint4(f2t(rb0.x), f2t(rb0.y), f2t(rb0.z), f2t(rb0.w));
    *(uint4*)&Bs[0][srow][skq + 4] = make_uint4(f2t(rb1.x), f2t(rb1.y), f2t(rb1.z), f2t(rb1.w));
    __syncthreads();

    const int nk = K / 16;
    for (int kc = 0; kc < nk; kc++) {
        const int p = kc & 1;
        if (kc + 1 < nk) {
            const float* Ap2 = Ap + (size_t)(kc + 1) * 16;
            const float* Bp2 = Bp + (size_t)(kc + 1) * 16;
            ra0 = *(const float4*)(Ap2);  ra1 = *(const float4*)(Ap2 + 4);
            rb0 = *(const float4*)(Bp2);  rb1 = *(const float4*)(Bp2 + 4);
        }
#pragma unroll
        for (int ks = 0; ks < 16; ks += 8) {
            uint32_t af[2][4], bf[8][2];
#pragma unroll
            for (int mt = 0; mt < 2; mt++) {
                const int r = wm * 32 + mt * 16 + g;
                af[mt][0] = As[p][r][ks + tg];
                af[mt][1] = As[p][r + 8][ks + tg];
                af[mt][2] = As[p][r][ks + tg + 4];
                af[mt][3] = As[p][r + 8][ks + tg + 4];
            }
#pragma unroll
            for (int nt = 0; nt < 8; nt++) {
                const int n = wn * 64 + nt * 8 + g;
                bf[nt][0] = Bs[p][n][ks + tg];
                bf[nt][1] = Bs[p][n][ks + tg + 4];
            }
#pragma unroll
            for (int mt = 0; mt < 2; mt++)
#pragma unroll
                for (int nt = 0; nt < 8; nt++)
                    mma8(acc[mt][nt], af[mt], bf[nt]);
        }
        if (kc + 1 < nk) {
            const int q = (kc + 1) & 1;
            *(uint4*)&As[q][srow][skq]     = make_uint4(f2t(ra0.x), f2t(ra0.y), f2t(ra0.z), f2t(ra0.w));
            *(uint4*)&As[q][srow][skq + 4] = make_uint4(f2t(ra1.x), f2t(ra1.y), f2t(ra1.z), f2t(ra1.w));
            *(uint4*)&Bs[q][srow][skq]     = make_uint4(f2t(rb0.x), f2t(rb0.y), f2t(rb0.z), f2t(rb0.w));
            *(uint4*)&Bs[q][srow][skq + 4] = make_uint4(f2t(rb1.x), f2t(rb1.y), f2t(rb1.z), f2t(rb1.w));
        }
        __syncthreads();
    }

    // epilogue
#pragma unroll
    for (int mt = 0; mt < 2; mt++) {
        const int r = row0 + wm * 32 + mt * 16 + g;
#pragma unroll
        for (int nt = 0; nt < 8; nt++) {
            const int cc = col0 + wn * 64 + nt * 8 + 2 * tg;
            float2 v0, v1;
            v0.x = acc[mt][nt][0] + bias[cc];
            v0.y = acc[mt][nt][1] + bias[cc + 1];
            v1.x = acc[mt][nt][2] + bias[cc];
            v1.y = acc[mt][nt][3] + bias[cc + 1];
            *(float2*)(C + (size_t)r * N + cc)       = v0;
            *(float2*)(C + (size_t)(r + 8) * N + cc) = v1;
        }
    }
}

// ---------------- scores (tf32 tensor): attn_raw = SCALE * Q @ K^T, lower-tri tiles ----
__global__ __launch_bounds__(256) void scores_tf32(
    const float* __restrict__ QKV, float* __restrict__ attn)
{
    const int kt = blockIdx.x, qt = blockIdx.y, z = blockIdx.z;
    if (kt > qt) return;
    const int b = z >> 4, h = z & 15;
    __shared__ uint32_t Qs[64][68];
    __shared__ uint32_t Ks[64][68];
    const int t = threadIdx.x, lane = t & 31, w = t >> 5;
    const int g = lane >> 2, tg = lane & 3;
    const int wm = w & 3, wn = w >> 2;

    const float* Qb = QKV + ((size_t)(b * SS) + qt * 64) * 3072 + h * 64;
    const float* Kb = QKV + ((size_t)(b * SS) + kt * 64) * 3072 + DD + h * 64;

    const int sr = t >> 2, sc = (t & 3) * 16;
#pragma unroll
    for (int i = 0; i < 16; i += 4) {
        float4 v = *(const float4*)(Qb + (size_t)sr * 3072 + sc + i);
        *(uint4*)&Qs[sr][sc + i] = make_uint4(f2t(v.x), f2t(v.y), f2t(v.z), f2t(v.w));
        v = *(const float4*)(Kb + (size_t)sr * 3072 + sc + i);
        *(uint4*)&Ks[sr][sc + i] = make_uint4(f2t(v.x), f2t(v.y), f2t(v.z), f2t(v.w));
    }
    __syncthreads();

    float acc[4][4];
#pragma unroll
    for (int nt = 0; nt < 4; nt++)
#pragma unroll
        for (int q = 0; q < 4; q++) acc[nt][q] = 0.f;

#pragma unroll
    for (int ks = 0; ks < 64; ks += 8) {
        uint32_t af[4];
        const int r = wm * 16 + g;
        af[0] = Qs[r][ks + tg];     af[1] = Qs[r + 8][ks + tg];
        af[2] = Qs[r][ks + tg + 4]; af[3] = Qs[r + 8][ks + tg + 4];
#pragma unroll
        for (int nt = 0; nt < 4; nt++) {
            uint32_t bf[2];
            const int n = wn * 32 + nt * 8 + g;
            bf[0] = Ks[n][ks + tg];
            bf[1] = Ks[n][ks + tg + 4];
            mma8(acc[nt], af, bf);
        }
    }

    const int r = qt * 64 + wm * 16 + g;
#pragma unroll
    for (int nt = 0; nt < 4; nt++) {
        const int cc = kt * 64 + wn * 32 + nt * 8 + 2 * tg;
        float2 v0, v1;
        v0.x = acc[nt][0] * ATT_SCALE;  v0.y = acc[nt][1] * ATT_SCALE;
        v1.x = acc[nt][2] * ATT_SCALE;  v1.y = acc[nt][3] * ATT_SCALE;
        *(float2*)(attn + ((size_t)z * SS + r) * SS + cc)     = v0;
        *(float2*)(attn + ((size_t)z * SS + r + 8) * SS + cc) = v1;
    }
}

// ---------------- row softmax with causal mask (writes zeros above diag) ----------
__global__ __launch_bounds__(256) void softmax_kernel(float* __restrict__ attn)
{
    const size_t row = blockIdx.x;           // row = z*S + q
    const int q = (int)(row & (SS - 1));
    float* p = attn + row * (size_t)SS;
    const int t = threadIdx.x;

    float v[8];
    float m = -1e30f;
#pragma unroll
    for (int l = 0; l < 8; l++) {
        const int i = t + l * 256;
        v[l] = (i <= q) ? p[i] : -1e30f;
        m = fmaxf(m, v[l]);
    }
#pragma unroll
    for (int o = 16; o > 0; o >>= 1) m = fmaxf(m, __shfl_xor_sync(0xffffffffu, m, o));
    __shared__ float redm[8];
    __shared__ float reds[8];
    if ((t & 31) == 0) redm[t >> 5] = m;
    __syncthreads();
    float bm = redm[0];
#pragma unroll
    for (int w = 1; w < 8; w++) bm = fmaxf(bm, redm[w]);

    float s = 0.f;
#pragma unroll
    for (int l = 0; l < 8; l++) {
        const int i = t + l * 256;
        v[l] = (i <= q) ? __expf(v[l] - bm) : 0.f;
        s += v[l];
    }
#pragma unroll
    for (int o = 16; o > 0; o >>= 1) s += __shfl_xor_sync(0xffffffffu, s, o);
    if ((t & 31) == 0) reds[t >> 5] = s;
    __syncthreads();
    float tot = 0.f;
#pragma unroll
    for (int w = 0; w < 8; w++) tot += reds[w];
    const float inv = 1.0f / tot;
#pragma unroll
    for (int l = 0; l < 8; l++) {
        const int i = t + l * 256;
        p[i] = v[l] * inv;
    }
}

// ---------------- ctx (tf32 tensor): ctx = attn @ V (causal k range) -> g_C ----------
__global__ __launch_bounds__(256) void ctx_tf32(
    const float* __restrict__ attn, const float* __restrict__ QKV,
    float* __restrict__ Cout)
{
    const int qt = blockIdx.x, z = blockIdx.y;
    const int b = z >> 4, h = z & 15;
    __shared__ uint32_t Ps[64][68];
    __shared__ uint32_t Vs[64][72];
    const int t = threadIdx.x, lane = t & 31, w = t >> 5;
    const int g = lane >> 2, tg = lane & 3;
    const int wm = w & 3, wn = w >> 2;

    const float* Pb = attn + ((size_t)z * SS + qt * 64) * SS;
    const float* Vb = QKV + (size_t)(b * SS) * 3072 + 2 * DD + h * 64;
    const int sr = t >> 2, sc = (t & 3) * 16;

    float acc[4][4];
#pragma unroll
    for (int nt = 0; nt < 4; nt++)
#pragma unroll
        for (int q = 0; q < 4; q++) acc[nt][q] = 0.f;

    for (int kt = 0; kt <= qt; kt++) {
#pragma unroll
        for (int i = 0; i < 16; i += 4) {
            float4 v = *(const float4*)(Pb + (size_t)sr * SS + kt * 64 + sc + i);
            *(uint4*)&Ps[sr][sc + i] = make_uint4(f2t(v.x), f2t(v.y), f2t(v.z), f2t(v.w));
            v = *(const float4*)(Vb + (size_t)(kt * 64 + sr) * 3072 + sc + i);
            *(uint4*)&Vs[sr][sc + i] = make_uint4(f2t(v.x), f2t(v.y), f2t(v.z), f2t(v.w));
        }
        __syncthreads();
#pragma unroll
        for (int ks = 0; ks < 64; ks += 8) {
            uint32_t af[4];
            const int r = wm * 16 + g;
            af[0] = Ps[r][ks + tg];     af[1] = Ps[r + 8][ks + tg];
            af[2] = Ps[r][ks + tg + 4]; af[3] = Ps[r + 8][ks + tg + 4];
#pragma unroll
            for (int nt = 0; nt < 4; nt++) {
                uint32_t bf[2];
                const int n = wn * 32 + nt * 8 + g;
                bf[0] = Vs[ks + tg][n];
                bf[1] = Vs[ks + tg + 4][n];
                mma8(acc[nt], af, bf);
            }
        }
        __syncthreads();
    }

    const int q = qt * 64 + wm * 16 + g;
    const int d = h * 64 + wn * 32;
#pragma unroll
    for (int nt = 0; nt < 4; nt++) {
        const int cc = d + nt * 8 + 2 * tg;
        float2 v0, v1;
        v0.x = acc[nt][0];  v0.y = acc[nt][1];
        v1.x = acc[nt][2];  v1.y = acc[nt][3];
        *(float2*)(Cout + ((size_t)(b * SS) + q) * DD + cc)     = v0;
        *(float2*)(Cout + ((size_t)(b * SS) + q + 8) * DD + cc) = v1;
    }
}

// ---------------- launch ----------------
extern "C" void kernel_launch(void* const* d_in, const int* in_sizes, int n_in,
                              void* d_out, int out_size)
{
    const float* x  = (const float*)d_in[0];
    const float* Wq = (const float*)d_in[1];
    const float* bq = (const float*)d_in[2];
    const float* Wk = (const float*)d_in[3];
    const float* bk = (const float*)d_in[4];
    const float* Wv = (const float*)d_in[5];
    const float* bv = (const float*)d_in[6];
    const float* Wo = (const float*)d_in[7];
    const float* bo = (const float*)d_in[8];

    float* out  = (float*)d_out;
    float* attn = out + (size_t)NR * DD;   // tuple order: (out, attn)

    float *pW3, *pb3, *pQKV, *pC;
    cudaGetSymbolAddress((void**)&pW3,  g_W3);
    cudaGetSymbolAddress((void**)&pb3,  g_b3);
    cudaGetSymbolAddress((void**)&pQKV, g_QKV);
    cudaGetSymbolAddress((void**)&pC,   g_C);

    // 1) concat weights/biases
    concat_kernel<<<(DD * DD + 255) / 256, 256>>>(Wq, Wk, Wv, bq, bk, bv);

    // 2) fused QKV projection: (4096 x 3072) = x @ W3^T + b3   [tf32 tensor]
    gemm_nt_tf32<<<dim3(3072 / 128, NR / 128), 256>>>(x, pW3, pb3, pQKV, NR, 3072, DD);

    // 3) raw causal scores into attn region [tf32 tensor]
    scores_tf32<<<dim3(SS / 64, SS / 64, BB * HH), 256>>>(pQKV, attn);

    // 4) softmax per row (also zero-fills masked region)
    softmax_kernel<<<BB * HH * SS, 256>>>(attn);

    // 5) ctx = attn @ V [tf32 tensor]
    ctx_tf32<<<dim3(SS / 64, BB * HH), 256>>>(attn, pQKV, pC);

    // 6) output projection [tf32 tensor]
    gemm_nt_tf32<<<dim3(DD / 128, NR / 128), 256>>>(pC, Wo, bo, out, NR, DD, DD);
}